// round 8
// baseline (speedup 1.0000x reference)
#include <cuda_runtime.h>
#include <cuda_fp16.h>
#include <math.h>
#include <stdint.h>

// Problem constants
#define B_  2
#define S_  2048
#define E_  2048
#define H_  32
#define HKV_ 8
#define D_  64
#define G_  4
#define M_  (B_*S_)   // 4096

// Scratch (device globals; no allocation allowed)
__device__ float g_Q[(size_t)B_*S_*H_*D_];
__device__ float g_K[(size_t)B_*S_*HKV_*D_];
__device__ float g_V[(size_t)B_*S_*HKV_*D_];
__device__ float g_A[(size_t)B_*S_*H_*D_];

// ---------------------------------------------------------------------------
// helpers
// ---------------------------------------------------------------------------
__device__ __forceinline__ uint32_t f22h2(float lo, float hi) {
    __half2 h = __floats2half2_rn(lo, hi);   // .x = lo (low 16 bits)
    return *(uint32_t*)&h;
}

// D += A(16x16) * B(16x8), fp16 operands, f32 accumulate.
__device__ __forceinline__ void mma16(float* c, const uint32_t* a, const uint32_t* b) {
    asm volatile(
        "mma.sync.aligned.m16n8k16.row.col.f32.f16.f16.f32 "
        "{%0,%1,%2,%3}, {%4,%5,%6,%7}, {%8,%9}, {%0,%1,%2,%3};"
        : "+f"(c[0]), "+f"(c[1]), "+f"(c[2]), "+f"(c[3])
        : "r"(a[0]), "r"(a[1]), "r"(a[2]), "r"(a[3]), "r"(b[0]), "r"(b[1]));
}

// Fragment layouts in SMEM (fragment-contiguous so frag load = LDS.128 / LDS.64):
//  A frag (16 rows x 16 k): word(r, p)  [p = k/2]  ->
//      lane = (r&7)*4 + (p&3), reg = (r>>3) + 2*(p>>2), 4 words/lane
//  B frag (16 k x 8 n):     word(p, n) ->
//      lane = n*4 + (p&3), reg = p>>2, 2 words/lane

// ---------------------------------------------------------------------------
// fp16 GEMM:  C[m][n] = sum_k A[m][k] * W[n][k]
// BM=128, BN=128, BK=32; 256 threads (8 warps, 2m x 4n), warp tile 64x32.
// ---------------------------------------------------------------------------
__global__ __launch_bounds__(256) void gemm_fp16(
    const float* __restrict__ A, const float* __restrict__ W,
    float* __restrict__ C, int M, int N, int K)
{
    __shared__ uint32_t sA[2048];   // 8 m-sub x 2 k-sub x 32 lanes x 4 words
    __shared__ uint32_t sB[2048];   // 16 n-sub x 2 k-sub x 32 lanes x 2 words

    int tid  = threadIdx.x;
    int lane = tid & 31;
    int wid  = tid >> 5;
    int wm   = wid >> 2;      // 0..1
    int wn   = wid & 3;       // 0..3
    int m0   = blockIdx.y * 128;
    int n0   = blockIdx.x * 128;

    float acc[4][4][4];
#pragma unroll
    for (int mi = 0; mi < 4; mi++)
#pragma unroll
        for (int ni = 0; ni < 4; ni++)
#pragma unroll
            for (int c = 0; c < 4; c++) acc[mi][ni][c] = 0.f;

    for (int k0 = 0; k0 < K; k0 += 32) {
        // Stage A tile 128x32 -> fp16 fragments
#pragma unroll
        for (int i = 0; i < 4; i++) {
            int lin = tid + i * 256;          // 1024 float4s
            int m   = lin >> 3;
            int kq  = (lin & 7) * 4;
            float4 v = *(const float4*)(A + (size_t)(m0 + m) * K + k0 + kq);
            int mi = m >> 4, r = m & 15, ki = kq >> 4, pp = (kq >> 1) & 7;
            int base = ((mi * 2 + ki) * 32 + (r & 7) * 4 + (pp & 3)) * 4
                     + (r >> 3) + 2 * (pp >> 2);
            sA[base]     = f22h2(v.x, v.y);
            sA[base + 4] = f22h2(v.z, v.w);
        }
        // Stage W tile 128x32
#pragma unroll
        for (int i = 0; i < 4; i++) {
            int lin = tid + i * 256;
            int n   = lin >> 3;
            int kq  = (lin & 7) * 4;
            float4 v = *(const float4*)(W + (size_t)(n0 + n) * K + k0 + kq);
            int ni = n >> 3, nr = n & 7, ki = kq >> 4, pp = (kq >> 1) & 7;
            int base = ((ni * 2 + ki) * 32 + nr * 4 + (pp & 3)) * 2 + (pp >> 2);
            sB[base]     = f22h2(v.x, v.y);
            sB[base + 2] = f22h2(v.z, v.w);
        }
        __syncthreads();

#pragma unroll
        for (int ki = 0; ki < 2; ki++) {
            uint32_t a[4][4];
            uint32_t b[4][2];
#pragma unroll
            for (int mi = 0; mi < 4; mi++)
                *(uint4*)a[mi] =
                    *(const uint4*)&sA[(((wm * 4 + mi) * 2 + ki) * 32 + lane) * 4];
#pragma unroll
            for (int ni = 0; ni < 4; ni++)
                *(uint2*)b[ni] =
                    *(const uint2*)&sB[(((wn * 4 + ni) * 2 + ki) * 32 + lane) * 2];
#pragma unroll
            for (int mi = 0; mi < 4; mi++)
#pragma unroll
                for (int ni = 0; ni < 4; ni++)
                    mma16(acc[mi][ni], a[mi], b[ni]);
        }
        __syncthreads();
    }

    // Epilogue
    int gr = lane >> 2;
    int gc = (lane & 3) * 2;
#pragma unroll
    for (int mi = 0; mi < 4; mi++) {
        int row = m0 + wm * 64 + mi * 16 + gr;
#pragma unroll
        for (int ni = 0; ni < 4; ni++) {
            int col = n0 + wn * 32 + ni * 8 + gc;
            *(float2*)(C + (size_t)row * N + col) =
                make_float2(acc[mi][ni][0], acc[mi][ni][1]);
            *(float2*)(C + (size_t)(row + 8) * N + col) =
                make_float2(acc[mi][ni][2], acc[mi][ni][3]);
        }
    }
}

// ---------------------------------------------------------------------------
// RoPE in-place on (B,S,nh,D) tensor. One thread per rotation pair.
// ---------------------------------------------------------------------------
__global__ void rope_kernel(float* __restrict__ T, const float* __restrict__ cosT,
                            const float* __restrict__ sinT, int nh, int total_pairs)
{
    int idx = blockIdx.x * blockDim.x + threadIdx.x;
    if (idx >= total_pairs) return;
    int d = idx & 31;
    int h = (idx >> 5) % nh;
    int s = (idx >> 5) / nh % S_;
    int b = idx / (32 * nh * S_);
    size_t base = (((size_t)b * S_ + s) * nh + h) * D_;
    float q1 = T[base + d];
    float q2 = T[base + d + 32];
    float c  = cosT[s * D_ + d];
    float sn = sinT[s * D_ + d];
    T[base + d]      = q1 * c - q2 * sn;
    T[base + d + 32] = q2 * c + q1 * sn;
}

// ---------------------------------------------------------------------------
// Flash attention with fp16 mma. BM=128 (8 warps x 16 rows), BN=64, D=64.
// SMEM 48KB -> 2 CTAs/SM.
//   sQ: 8 m-sub x 4 kd  x 32 x 4 = 4096 words (A frags, Q pre-scaled)
//   sK: 4 kd    x 8 ntok x 32 x 2 = 2048 words (B frags)
//   sV: 4 ktok  x 8 nd   x 32 x 2 = 2048 words (B frags; halves packed per token parity)
//   sP: 8 m-sub x 4 ktok x 32 x 4 = 4096 words (A frags)
// ---------------------------------------------------------------------------
#define SQ_OFF 0
#define SK_OFF 4096
#define SV_OFF 6144
#define SP_OFF 8192
#define FLASH_SMEM (12288 * 4)

__global__ __launch_bounds__(256, 2) void flash_fp16(
    const float* __restrict__ Qg, const float* __restrict__ Kg,
    const float* __restrict__ Vg, float* __restrict__ Og)
{
    extern __shared__ uint32_t smf[];
    __half* sVh = (__half*)(smf + SV_OFF);

    int tid  = threadIdx.x;
    int lane = tid & 31;
    int wid  = tid >> 5;
    int q0   = blockIdx.x * 128;
    int h    = blockIdx.y;
    int b    = blockIdx.z;
    int hk   = h >> 2;
    int t    = lane & 3;
    int rlo  = lane >> 2;

    // Load Q tile (scaled by 1/8) into A-fragment layout
#pragma unroll
    for (int i = 0; i < 8; i++) {
        int lin = tid + i * 256;              // 2048 float4s
        int m   = lin >> 4;
        int d0  = (lin & 15) * 4;
        float4 v = *(const float4*)(Qg + ((((size_t)b * S_ + q0 + m) * H_ + h) * D_) + d0);
        int mi = m >> 4, r = m & 15, ki = d0 >> 4, pp = (d0 >> 1) & 7;
        int base = SQ_OFF + ((mi * 4 + ki) * 32 + (r & 7) * 4 + (pp & 3)) * 4
                 + (r >> 3) + 2 * (pp >> 2);
        smf[base]     = f22h2(v.x * 0.125f, v.y * 0.125f);
        smf[base + 4] = f22h2(v.z * 0.125f, v.w * 0.125f);
    }

    float o[8][4];
#pragma unroll
    for (int ni = 0; ni < 8; ni++)
#pragma unroll
        for (int c = 0; c < 4; c++) o[ni][c] = 0.f;
    float mlo = -INFINITY, mhi = -INFINITY;
    float llo = 0.f, lhi = 0.f;

    for (int t0 = 0; t0 < S_; t0 += 64) {
        __syncthreads();
        // Stage K and V tiles (64 tokens x 64 d)
#pragma unroll
        for (int i = 0; i < 4; i++) {
            int lin = tid + i * 256;           // 1024 float4s
            int n   = lin >> 4;                // kv token in tile
            int d0  = (lin & 15) * 4;
            size_t gidx = (((size_t)b * S_ + t0 + n) * HKV_ + hk) * D_ + d0;
            float4 kv = *(const float4*)(Kg + gidx);
            {   // K B-frag: k-dim = d, n-dim = token
                int ki = d0 >> 4, pp = (d0 >> 1) & 7, ni = n >> 3, nr = n & 7;
                int base = SK_OFF + ((ki * 8 + ni) * 32 + nr * 4 + (pp & 3)) * 2
                         + (pp >> 2);
                smf[base]     = f22h2(kv.x, kv.y);
                smf[base + 2] = f22h2(kv.z, kv.w);
            }
            float4 vv = *(const float4*)(Vg + gidx);
            {   // V B-frag: k-dim = token, n-dim = d; token parity selects half
                int kt = n >> 4, pp = (n >> 1) & 7, reg = pp >> 2, half = n & 1;
                int nd = d0 >> 3;
                float vals[4] = {vv.x, vv.y, vv.z, vv.w};
#pragma unroll
                for (int j = 0; j < 4; j++) {
                    int dr = (d0 & 7) + j;
                    int idx = ((kt * 8 + nd) * 32 + dr * 4 + (pp & 3)) * 2 + reg;
                    sVh[idx * 2 + half] = __float2half_rn(vals[j]);
                }
            }
        }
        __syncthreads();

        // S = Q K^T  (16 x 64 per warp)
        float s[8][4];
#pragma unroll
        for (int ni = 0; ni < 8; ni++)
#pragma unroll
            for (int c = 0; c < 4; c++) s[ni][c] = 0.f;

#pragma unroll
        for (int ks = 0; ks < 4; ks++) {
            uint32_t a[4];
            *(uint4*)a = *(const uint4*)&smf[SQ_OFF + ((wid * 4 + ks) * 32 + lane) * 4];
#pragma unroll
            for (int ni = 0; ni < 8; ni++) {
                uint32_t bb[2];
                *(uint2*)bb = *(const uint2*)&smf[SK_OFF + ((ks * 8 + ni) * 32 + lane) * 2];
                mma16(s[ni], a, bb);
            }
        }

        // Online softmax. Thread owns cols {ni*8 + 2t, +1} of rows rlo, rlo+8.
        float vmlo = -INFINITY, vmhi = -INFINITY;
#pragma unroll
        for (int ni = 0; ni < 8; ni++) {
            vmlo = fmaxf(vmlo, fmaxf(s[ni][0], s[ni][1]));
            vmhi = fmaxf(vmhi, fmaxf(s[ni][2], s[ni][3]));
        }
        vmlo = fmaxf(vmlo, __shfl_xor_sync(0xffffffffu, vmlo, 1));
        vmlo = fmaxf(vmlo, __shfl_xor_sync(0xffffffffu, vmlo, 2));
        vmhi = fmaxf(vmhi, __shfl_xor_sync(0xffffffffu, vmhi, 1));
        vmhi = fmaxf(vmhi, __shfl_xor_sync(0xffffffffu, vmhi, 2));

        float mnlo = fmaxf(mlo, vmlo);
        float mnhi = fmaxf(mhi, vmhi);
        float alo  = __expf(mlo - mnlo);
        float ahi  = __expf(mhi - mnhi);
        mlo = mnlo; mhi = mnhi;

        float sl = 0.f, sh = 0.f;
#pragma unroll
        for (int ni = 0; ni < 8; ni++) {
            float p0 = __expf(s[ni][0] - mnlo);
            float p1 = __expf(s[ni][1] - mnlo);
            float p2 = __expf(s[ni][2] - mnhi);
            float p3 = __expf(s[ni][3] - mnhi);
            sl += p0 + p1;
            sh += p2 + p3;
            // P A-frag store: own lane, kt = ni>>1, reg = 2*(ni&1) (+1 for high rows)
            int base = SP_OFF + ((wid * 4 + (ni >> 1)) * 32 + lane) * 4 + (ni & 1) * 2;
            smf[base]     = f22h2(p0, p1);
            smf[base + 1] = f22h2(p2, p3);
            o[ni][0] *= alo; o[ni][1] *= alo;
            o[ni][2] *= ahi; o[ni][3] *= ahi;
        }
        llo = llo * alo + sl;
        lhi = lhi * ahi + sh;
        __syncwarp();

        // O += P @ V
#pragma unroll
        for (int kt = 0; kt < 4; kt++) {
            uint32_t a[4];
            *(uint4*)a = *(const uint4*)&smf[SP_OFF + ((wid * 4 + kt) * 32 + lane) * 4];
#pragma unroll
            for (int ni = 0; ni < 8; ni++) {
                uint32_t bb[2];
                *(uint2*)bb = *(const uint2*)&smf[SV_OFF + ((kt * 8 + ni) * 32 + lane) * 2];
                mma16(o[ni], a, bb);
            }
        }
    }

    // Epilogue: finish l reduction across lane quad, normalize, store
    llo += __shfl_xor_sync(0xffffffffu, llo, 1);
    llo += __shfl_xor_sync(0xffffffffu, llo, 2);
    lhi += __shfl_xor_sync(0xffffffffu, lhi, 1);
    lhi += __shfl_xor_sync(0xffffffffu, lhi, 2);
    float ilo = 1.f / llo;
    float ihi = 1.f / lhi;

    int row = q0 + wid * 16 + rlo;
#pragma unroll
    for (int ni = 0; ni < 8; ni++) {
        int d = ni * 8 + t * 2;
        size_t glo = (((size_t)b * S_ + row) * H_ + h) * D_ + d;
        *(float2*)(Og + glo) = make_float2(o[ni][0] * ilo, o[ni][1] * ilo);
        size_t ghi = (((size_t)b * S_ + row + 8) * H_ + h) * D_ + d;
        *(float2*)(Og + ghi) = make_float2(o[ni][2] * ihi, o[ni][3] * ihi);
    }
}

// ---------------------------------------------------------------------------
extern "C" void kernel_launch(void* const* d_in, const int* in_sizes, int n_in,
                              void* d_out, int out_size)
{
    const float* x    = (const float*)d_in[0];
    const float* cosT = (const float*)d_in[1];
    const float* sinT = (const float*)d_in[2];
    const float* Wq   = (const float*)d_in[3];
    const float* Wk   = (const float*)d_in[4];
    const float* Wv   = (const float*)d_in[5];
    const float* Wo   = (const float*)d_in[6];
    float* out = (float*)d_out;

    float *Q, *K, *V, *A;
    cudaGetSymbolAddress((void**)&Q, g_Q);
    cudaGetSymbolAddress((void**)&K, g_K);
    cudaGetSymbolAddress((void**)&V, g_V);
    cudaGetSymbolAddress((void**)&A, g_A);

    // Projections (fp16 tensor cores, f32 accumulate)
    gemm_fp16<<<dim3(E_ / 128, M_ / 128), 256>>>(x, Wq, Q, M_, E_, E_);
    gemm_fp16<<<dim3((HKV_ * D_) / 128, M_ / 128), 256>>>(x, Wk, K, M_, HKV_ * D_, E_);
    gemm_fp16<<<dim3((HKV_ * D_) / 128, M_ / 128), 256>>>(x, Wv, V, M_, HKV_ * D_, E_);

    // RoPE
    {
        int pq = B_ * S_ * H_ * 32;
        rope_kernel<<<(pq + 255) / 256, 256>>>(Q, cosT, sinT, H_, pq);
        int pk = B_ * S_ * HKV_ * 32;
        rope_kernel<<<(pk + 255) / 256, 256>>>(K, cosT, sinT, HKV_, pk);
    }

    // Flash attention (fp16 tensor cores)
    {
        cudaFuncSetAttribute(flash_fp16, cudaFuncAttributeMaxDynamicSharedMemorySize,
                             FLASH_SMEM);
        flash_fp16<<<dim3(S_ / 128, H_, B_), 256, FLASH_SMEM>>>(Q, K, V, A);
    }

    // Output projection
    gemm_fp16<<<dim3(E_ / 128, M_ / 128), 256>>>(A, Wo, out, M_, E_, E_);
}

// round 10
// speedup vs baseline: 1.0121x; 1.0121x over previous
#include <cuda_runtime.h>
#include <cuda_fp16.h>
#include <math.h>
#include <stdint.h>

// Problem constants
#define B_  2
#define S_  2048
#define E_  2048
#define H_  32
#define HKV_ 8
#define D_  64
#define G_  4
#define M_  (B_*S_)   // 4096

// Scratch (device globals; no allocation allowed)
__device__ float g_Q[(size_t)B_*S_*H_*D_];
__device__ float g_K[(size_t)B_*S_*HKV_*D_];
__device__ float g_V[(size_t)B_*S_*HKV_*D_];
__device__ float g_A[(size_t)B_*S_*H_*D_];

// ---------------------------------------------------------------------------
// helpers
// ---------------------------------------------------------------------------
__device__ __forceinline__ uint32_t f22h2(float lo, float hi) {
    __half2 h = __floats2half2_rn(lo, hi);   // .x = lo (low 16 bits)
    return *(uint32_t*)&h;
}

// D += A(16x16) * B(16x8), fp16 operands, f32 accumulate.
__device__ __forceinline__ void mma16(float* c, const uint32_t* a, const uint32_t* b) {
    asm volatile(
        "mma.sync.aligned.m16n8k16.row.col.f32.f16.f16.f32 "
        "{%0,%1,%2,%3}, {%4,%5,%6,%7}, {%8,%9}, {%0,%1,%2,%3};"
        : "+f"(c[0]), "+f"(c[1]), "+f"(c[2]), "+f"(c[3])
        : "r"(a[0]), "r"(a[1]), "r"(a[2]), "r"(a[3]), "r"(b[0]), "r"(b[1]));
}

// Fragment layouts in SMEM (fragment-contiguous so frag load = LDS.128 / LDS.64):
//  A frag (16 rows x 16 k): word(r, p)  [p = k/2]  ->
//      lane = (r&7)*4 + (p&3), reg = (r>>3) + 2*(p>>2), 4 words/lane
//  B frag (16 k x 8 n):     word(p, n) ->
//      lane = n*4 + (p&3), reg = p>>2, 2 words/lane

// ---------------------------------------------------------------------------
// fp16 GEMM:  C[m][n] = sum_k A[m][k] * W[n][k]
// BM=128, BN=128, BK=32; 256 threads (8 warps, 2m x 4n), warp tile 64x32.
// ---------------------------------------------------------------------------
__global__ __launch_bounds__(256) void gemm_fp16(
    const float* __restrict__ A, const float* __restrict__ W,
    float* __restrict__ C, int M, int N, int K)
{
    __shared__ uint32_t sA[2048];   // 8 m-sub x 2 k-sub x 32 lanes x 4 words
    __shared__ uint32_t sB[2048];   // 16 n-sub x 2 k-sub x 32 lanes x 2 words

    int tid  = threadIdx.x;
    int lane = tid & 31;
    int wid  = tid >> 5;
    int wm   = wid >> 2;      // 0..1
    int wn   = wid & 3;       // 0..3
    int m0   = blockIdx.y * 128;
    int n0   = blockIdx.x * 128;

    float acc[4][4][4];
#pragma unroll
    for (int mi = 0; mi < 4; mi++)
#pragma unroll
        for (int ni = 0; ni < 4; ni++)
#pragma unroll
            for (int c = 0; c < 4; c++) acc[mi][ni][c] = 0.f;

    for (int k0 = 0; k0 < K; k0 += 32) {
        // Stage A tile 128x32 -> fp16 fragments
#pragma unroll
        for (int i = 0; i < 4; i++) {
            int lin = tid + i * 256;          // 1024 float4s
            int m   = lin >> 3;
            int kq  = (lin & 7) * 4;
            float4 v = *(const float4*)(A + (size_t)(m0 + m) * K + k0 + kq);
            int mi = m >> 4, r = m & 15, ki = kq >> 4, pp = (kq >> 1) & 7;
            int base = ((mi * 2 + ki) * 32 + (r & 7) * 4 + (pp & 3)) * 4
                     + (r >> 3) + 2 * (pp >> 2);
            sA[base]     = f22h2(v.x, v.y);
            sA[base + 4] = f22h2(v.z, v.w);
        }
        // Stage W tile 128x32
#pragma unroll
        for (int i = 0; i < 4; i++) {
            int lin = tid + i * 256;
            int n   = lin >> 3;
            int kq  = (lin & 7) * 4;
            float4 v = *(const float4*)(W + (size_t)(n0 + n) * K + k0 + kq);
            int ni = n >> 3, nr = n & 7, ki = kq >> 4, pp = (kq >> 1) & 7;
            int base = ((ni * 2 + ki) * 32 + nr * 4 + (pp & 3)) * 2 + (pp >> 2);
            sB[base]     = f22h2(v.x, v.y);
            sB[base + 2] = f22h2(v.z, v.w);
        }
        __syncthreads();

#pragma unroll
        for (int ki = 0; ki < 2; ki++) {
            uint32_t a[4][4];
            uint32_t b[4][2];
#pragma unroll
            for (int mi = 0; mi < 4; mi++)
                *(uint4*)a[mi] =
                    *(const uint4*)&sA[(((wm * 4 + mi) * 2 + ki) * 32 + lane) * 4];
#pragma unroll
            for (int ni = 0; ni < 4; ni++)
                *(uint2*)b[ni] =
                    *(const uint2*)&sB[(((wn * 4 + ni) * 2 + ki) * 32 + lane) * 2];
#pragma unroll
            for (int mi = 0; mi < 4; mi++)
#pragma unroll
                for (int ni = 0; ni < 4; ni++)
                    mma16(acc[mi][ni], a[mi], b[ni]);
        }
        __syncthreads();
    }

    // Epilogue
    int gr = lane >> 2;
    int gc = (lane & 3) * 2;
#pragma unroll
    for (int mi = 0; mi < 4; mi++) {
        int row = m0 + wm * 64 + mi * 16 + gr;
#pragma unroll
        for (int ni = 0; ni < 4; ni++) {
            int col = n0 + wn * 32 + ni * 8 + gc;
            *(float2*)(C + (size_t)row * N + col) =
                make_float2(acc[mi][ni][0], acc[mi][ni][1]);
            *(float2*)(C + (size_t)(row + 8) * N + col) =
                make_float2(acc[mi][ni][2], acc[mi][ni][3]);
        }
    }
}

// ---------------------------------------------------------------------------
// RoPE in-place on (B,S,nh,D) tensor. One thread per rotation pair.
// ---------------------------------------------------------------------------
__global__ void rope_kernel(float* __restrict__ T, const float* __restrict__ cosT,
                            const float* __restrict__ sinT, int nh, int total_pairs)
{
    int idx = blockIdx.x * blockDim.x + threadIdx.x;
    if (idx >= total_pairs) return;
    int d = idx & 31;
    int h = (idx >> 5) % nh;
    int s = (idx >> 5) / nh % S_;
    int b = idx / (32 * nh * S_);
    size_t base = (((size_t)b * S_ + s) * nh + h) * D_;
    float q1 = T[base + d];
    float q2 = T[base + d + 32];
    float c  = cosT[s * D_ + d];
    float sn = sinT[s * D_ + d];
    T[base + d]      = q1 * c - q2 * sn;
    T[base + d + 32] = q2 * c + q1 * sn;
}

// ---------------------------------------------------------------------------
// Flash attention with fp16 mma. BM=128 (8 warps x 16 rows), BN=64, D=64.
// SMEM 48KB -> 2 CTAs/SM.
//   sQ: 8 m-sub x 4 kd  x 32 x 4 = 4096 words (A frags, Q pre-scaled)
//   sK: 4 kd    x 8 ntok x 32 x 2 = 2048 words (B frags)
//   sV: 4 ktok  x 8 nd   x 32 x 2 = 2048 words (B frags; halves packed per token parity)
//   sP: 8 m-sub x 4 ktok x 32 x 4 = 4096 words (A frags)
// ---------------------------------------------------------------------------
#define SQ_OFF 0
#define SK_OFF 4096
#define SV_OFF 6144
#define SP_OFF 8192
#define FLASH_SMEM (12288 * 4)

__global__ __launch_bounds__(256, 2) void flash_fp16(
    const float* __restrict__ Qg, const float* __restrict__ Kg,
    const float* __restrict__ Vg, float* __restrict__ Og)
{
    extern __shared__ uint32_t smf[];
    __half* sVh = (__half*)(smf + SV_OFF);

    int tid  = threadIdx.x;
    int lane = tid & 31;
    int wid  = tid >> 5;
    int q0   = blockIdx.x * 128;
    int h    = blockIdx.y;
    int b    = blockIdx.z;
    int hk   = h >> 2;
    int t    = lane & 3;
    int rlo  = lane >> 2;

    // Load Q tile (scaled by 1/8) into A-fragment layout
#pragma unroll
    for (int i = 0; i < 8; i++) {
        int lin = tid + i * 256;              // 2048 float4s
        int m   = lin >> 4;
        int d0  = (lin & 15) * 4;
        float4 v = *(const float4*)(Qg + ((((size_t)b * S_ + q0 + m) * H_ + h) * D_) + d0);
        int mi = m >> 4, r = m & 15, ki = d0 >> 4, pp = (d0 >> 1) & 7;
        int base = SQ_OFF + ((mi * 4 + ki) * 32 + (r & 7) * 4 + (pp & 3)) * 4
                 + (r >> 3) + 2 * (pp >> 2);
        smf[base]     = f22h2(v.x * 0.125f, v.y * 0.125f);
        smf[base + 4] = f22h2(v.z * 0.125f, v.w * 0.125f);
    }

    float o[8][4];
#pragma unroll
    for (int ni = 0; ni < 8; ni++)
#pragma unroll
        for (int c = 0; c < 4; c++) o[ni][c] = 0.f;
    float mlo = -INFINITY, mhi = -INFINITY;
    float llo = 0.f, lhi = 0.f;

    for (int t0 = 0; t0 < S_; t0 += 64) {
        __syncthreads();
        // Stage K and V tiles (64 tokens x 64 d)
#pragma unroll
        for (int i = 0; i < 4; i++) {
            int lin = tid + i * 256;           // 1024 float4s
            int n   = lin >> 4;                // kv token in tile
            int d0  = (lin & 15) * 4;
            size_t gidx = (((size_t)b * S_ + t0 + n) * HKV_ + hk) * D_ + d0;
            float4 kv = *(const float4*)(Kg + gidx);
            {   // K B-frag: k-dim = d, n-dim = token
                int ki = d0 >> 4, pp = (d0 >> 1) & 7, ni = n >> 3, nr = n & 7;
                int base = SK_OFF + ((ki * 8 + ni) * 32 + nr * 4 + (pp & 3)) * 2
                         + (pp >> 2);
                smf[base]     = f22h2(kv.x, kv.y);
                smf[base + 2] = f22h2(kv.z, kv.w);
            }
            float4 vv = *(const float4*)(Vg + gidx);
            {   // V B-frag: k-dim = token, n-dim = d; token parity selects half
                int kt = n >> 4, pp = (n >> 1) & 7, reg = pp >> 2, half = n & 1;
                int nd = d0 >> 3;
                float vals[4] = {vv.x, vv.y, vv.z, vv.w};
#pragma unroll
                for (int j = 0; j < 4; j++) {
                    int dr = (d0 & 7) + j;
                    int idx = ((kt * 8 + nd) * 32 + dr * 4 + (pp & 3)) * 2 + reg;
                    sVh[idx * 2 + half] = __float2half_rn(vals[j]);
                }
            }
        }
        __syncthreads();

        // S = Q K^T  (16 x 64 per warp)
        float s[8][4];
#pragma unroll
        for (int ni = 0; ni < 8; ni++)
#pragma unroll
            for (int c = 0; c < 4; c++) s[ni][c] = 0.f;

#pragma unroll
        for (int ks = 0; ks < 4; ks++) {
            uint32_t a[4];
            *(uint4*)a = *(const uint4*)&smf[SQ_OFF + ((wid * 4 + ks) * 32 + lane) * 4];
#pragma unroll
            for (int ni = 0; ni < 8; ni++) {
                uint32_t bb[2];
                *(uint2*)bb = *(const uint2*)&smf[SK_OFF + ((ks * 8 + ni) * 32 + lane) * 2];
                mma16(s[ni], a, bb);
            }
        }

        // Online softmax. Thread owns cols {ni*8 + 2t, +1} of rows rlo, rlo+8.
        float vmlo = -INFINITY, vmhi = -INFINITY;
#pragma unroll
        for (int ni = 0; ni < 8; ni++) {
            vmlo = fmaxf(vmlo, fmaxf(s[ni][0], s[ni][1]));
            vmhi = fmaxf(vmhi, fmaxf(s[ni][2], s[ni][3]));
        }
        vmlo = fmaxf(vmlo, __shfl_xor_sync(0xffffffffu, vmlo, 1));
        vmlo = fmaxf(vmlo, __shfl_xor_sync(0xffffffffu, vmlo, 2));
        vmhi = fmaxf(vmhi, __shfl_xor_sync(0xffffffffu, vmhi, 1));
        vmhi = fmaxf(vmhi, __shfl_xor_sync(0xffffffffu, vmhi, 2));

        float mnlo = fmaxf(mlo, vmlo);
        float mnhi = fmaxf(mhi, vmhi);
        float alo  = __expf(mlo - mnlo);
        float ahi  = __expf(mhi - mnhi);
        mlo = mnlo; mhi = mnhi;

        float sl = 0.f, sh = 0.f;
#pragma unroll
        for (int ni = 0; ni < 8; ni++) {
            float p0 = __expf(s[ni][0] - mnlo);
            float p1 = __expf(s[ni][1] - mnlo);
            float p2 = __expf(s[ni][2] - mnhi);
            float p3 = __expf(s[ni][3] - mnhi);
            sl += p0 + p1;
            sh += p2 + p3;
            // P A-frag store: own lane, kt = ni>>1, reg = 2*(ni&1) (+1 for high rows)
            int base = SP_OFF + ((wid * 4 + (ni >> 1)) * 32 + lane) * 4 + (ni & 1) * 2;
            smf[base]     = f22h2(p0, p1);
            smf[base + 1] = f22h2(p2, p3);
            o[ni][0] *= alo; o[ni][1] *= alo;
            o[ni][2] *= ahi; o[ni][3] *= ahi;
        }
        llo = llo * alo + sl;
        lhi = lhi * ahi + sh;
        __syncwarp();

        // O += P @ V
#pragma unroll
        for (int kt = 0; kt < 4; kt++) {
            uint32_t a[4];
            *(uint4*)a = *(const uint4*)&smf[SP_OFF + ((wid * 4 + kt) * 32 + lane) * 4];
#pragma unroll
            for (int ni = 0; ni < 8; ni++) {
                uint32_t bb[2];
                *(uint2*)bb = *(const uint2*)&smf[SV_OFF + ((kt * 8 + ni) * 32 + lane) * 2];
                mma16(o[ni], a, bb);
            }
        }
    }

    // Epilogue: finish l reduction across lane quad, normalize, store
    llo += __shfl_xor_sync(0xffffffffu, llo, 1);
    llo += __shfl_xor_sync(0xffffffffu, llo, 2);
    lhi += __shfl_xor_sync(0xffffffffu, lhi, 1);
    lhi += __shfl_xor_sync(0xffffffffu, lhi, 2);
    float ilo = 1.f / llo;
    float ihi = 1.f / lhi;

    int row = q0 + wid * 16 + rlo;
#pragma unroll
    for (int ni = 0; ni < 8; ni++) {
        int d = ni * 8 + t * 2;
        size_t glo = (((size_t)b * S_ + row) * H_ + h) * D_ + d;
        *(float2*)(Og + glo) = make_float2(o[ni][0] * ilo, o[ni][1] * ilo);
        size_t ghi = (((size_t)b * S_ + row + 8) * H_ + h) * D_ + d;
        *(float2*)(Og + ghi) = make_float2(o[ni][2] * ihi, o[ni][3] * ihi);
    }
}

// ---------------------------------------------------------------------------
extern "C" void kernel_launch(void* const* d_in, const int* in_sizes, int n_in,
                              void* d_out, int out_size)
{
    const float* x    = (const float*)d_in[0];
    const float* cosT = (const float*)d_in[1];
    const float* sinT = (const float*)d_in[2];
    const float* Wq   = (const float*)d_in[3];
    const float* Wk   = (const float*)d_in[4];
    const float* Wv   = (const float*)d_in[5];
    const float* Wo   = (const float*)d_in[6];
    float* out = (float*)d_out;

    float *Q, *K, *V, *A;
    cudaGetSymbolAddress((void**)&Q, g_Q);
    cudaGetSymbolAddress((void**)&K, g_K);
    cudaGetSymbolAddress((void**)&V, g_V);
    cudaGetSymbolAddress((void**)&A, g_A);

    // Projections (fp16 tensor cores, f32 accumulate)
    gemm_fp16<<<dim3(E_ / 128, M_ / 128), 256>>>(x, Wq, Q, M_, E_, E_);
    gemm_fp16<<<dim3((HKV_ * D_) / 128, M_ / 128), 256>>>(x, Wk, K, M_, HKV_ * D_, E_);
    gemm_fp16<<<dim3((HKV_ * D_) / 128, M_ / 128), 256>>>(x, Wv, V, M_, HKV_ * D_, E_);

    // RoPE
    {
        int pq = B_ * S_ * H_ * 32;
        rope_kernel<<<(pq + 255) / 256, 256>>>(Q, cosT, sinT, H_, pq);
        int pk = B_ * S_ * HKV_ * 32;
        rope_kernel<<<(pk + 255) / 256, 256>>>(K, cosT, sinT, HKV_, pk);
    }

    // Flash attention (fp16 tensor cores)
    {
        cudaFuncSetAttribute(flash_fp16, cudaFuncAttributeMaxDynamicSharedMemorySize,
                             FLASH_SMEM);
        flash_fp16<<<dim3(S_ / 128, H_, B_), 256, FLASH_SMEM>>>(Q, K, V, A);
    }

    // Output projection
    gemm_fp16<<<dim3(E_ / 128, M_ / 128), 256>>>(A, Wo, out, M_, E_, E_);
}